// round 3
// baseline (speedup 1.0000x reference)
#include <cuda_runtime.h>

// lp[r,p] = sum_f w[p,f]^2 * sum_e x[r,f,e]^2
// x: [R=32768, F=64, E=16] fp32 (row = 1024 contiguous floats = 4KB)
// w: [P=10, F=64] fp32
// out: [R, P=10] fp32
//
// Strategy: warp-per-row (grid-stride). Each thread loads 8 float4s
// (coalesced: warp slot j covers float4 indices j*32..j*32+31 of the row).
// Each float4 lies entirely within one f (f = 8*j + lane/4). Per-thread
// 10 accumulators acc[p] += wsq[p][f] * sum4sq; butterfly warp reduce;
// lane 0 writes the 10 outputs.

#define R_ROWS 32768
#define F_DIM 64
#define E_DIM 16
#define P_DIM 10
#define THREADS 256
#define BLOCKS 592   // 4 blocks-worth of warps per SM equivalent; grid-stride

__global__ __launch_bounds__(THREADS) void ip_fused_kernel(
    const float* __restrict__ x,
    const float* __restrict__ w,
    float* __restrict__ out)
{
    __shared__ float sh_wsq[P_DIM * F_DIM];  // [p][f], pre-squared

    // Fill shared with w^2 (640 floats)
    for (int i = threadIdx.x; i < P_DIM * F_DIM; i += THREADS) {
        float v = w[i];
        sh_wsq[i] = v * v;
    }
    __syncthreads();

    const int lane = threadIdx.x & 31;
    const int warp = threadIdx.x >> 5;
    const int gwarp = blockIdx.x * (THREADS / 32) + warp;
    const int nwarp = gridDim.x * (THREADS / 32);

    const int fbase = lane >> 2;  // f = 8*j + fbase

    for (int r = gwarp; r < R_ROWS; r += nwarp) {
        const float4* __restrict__ xr =
            reinterpret_cast<const float4*>(x + (size_t)r * (F_DIM * E_DIM));

        // Issue all 8 loads up front (8-deep MLP per warp), streaming hint.
        float4 v[8];
#pragma unroll
        for (int j = 0; j < 8; ++j) {
            v[j] = __ldcs(&xr[j * 32 + lane]);
        }

        float acc[P_DIM];
#pragma unroll
        for (int p = 0; p < P_DIM; ++p) acc[p] = 0.0f;

#pragma unroll
        for (int j = 0; j < 8; ++j) {
            float s = fmaf(v[j].x, v[j].x,
                      fmaf(v[j].y, v[j].y,
                      fmaf(v[j].z, v[j].z, v[j].w * v[j].w)));
            const int f = 8 * j + fbase;
            // sh_wsq[p*64 + f]: 8 distinct banks, 4-way broadcast -> conflict-free
#pragma unroll
            for (int p = 0; p < P_DIM; ++p) {
                acc[p] = fmaf(sh_wsq[p * F_DIM + f], s, acc[p]);
            }
        }

        // Butterfly reduce all 10 accumulators across the warp.
#pragma unroll
        for (int p = 0; p < P_DIM; ++p) {
#pragma unroll
            for (int m = 16; m >= 1; m >>= 1) {
                acc[p] += __shfl_xor_sync(0xFFFFFFFFu, acc[p], m);
            }
        }

        if (lane == 0) {
            float* o = out + (size_t)r * P_DIM;
#pragma unroll
            for (int p = 0; p < P_DIM; ++p) o[p] = acc[p];
        }
    }
}

extern "C" void kernel_launch(void* const* d_in, const int* in_sizes, int n_in,
                              void* d_out, int out_size)
{
    const float* x = (const float*)d_in[0];   // [32768, 64, 16]
    const float* w = (const float*)d_in[1];   // [10, 64]
    float* out = (float*)d_out;               // [32768, 10]
    (void)in_sizes; (void)n_in; (void)out_size;

    ip_fused_kernel<<<BLOCKS, THREADS>>>(x, w, out);
}

// round 4
// speedup vs baseline: 1.2035x; 1.2035x over previous
#include <cuda_runtime.h>

// lp[r,p] = sum_f w[p,f]^2 * sum_e x[r,f,e]^2
// x: [R=32768, F=64, E=16] fp32 (row = 1024 contiguous floats = 4KB)
// w: [P=10, F=64] fp32 ; out: [R, 10] fp32
//
// Warp-per-row. lane = 4q + c (q=lane>>2, c=lane&3).
// Thread loads v[j] = float4 #(j*32+lane) of the row (coalesced), which lies
// in f = 8j+q, covering e = 4c..4c+3. Quad-butterfly (xor 1,2) yields the
// full S_f = sum_e x[r,f,e]^2 in every lane of the quad. Each lane then owns
// p in {c, c+4, c+8} (padded weights make p>=10 zero), 8 f's per row ->
// 3 accumulators, 24 FFMA, 24 conflict-free LDS. Cross-quad butterfly
// (xor 4,8,16) finishes the f-sum; lanes 0..9 store out[r*10+lane].

#define R_ROWS 32768
#define F_DIM 64
#define E_DIM 16
#define P_DIM 10
#define P_PAD 12
#define THREADS 256
#define BLOCKS 592   // 4 blocks/SM * 148 SMs; grid-stride over rows

__global__ __launch_bounds__(THREADS, 4) void ip_fused_kernel(
    const float* __restrict__ x,
    const float* __restrict__ w,
    float* __restrict__ out)
{
    // [f][12] layout: word addr = f*12 + p. For the access pattern
    // (8j+q)*12 + 4t + c, banks (12q+c) mod 32 are all distinct -> conflict-free.
    __shared__ float sh_wsq[F_DIM * P_PAD];

    for (int i = threadIdx.x; i < F_DIM * P_PAD; i += THREADS) {
        const int f = i / P_PAD;
        const int p = i - f * P_PAD;
        float v = (p < P_DIM) ? w[p * F_DIM + f] : 0.0f;
        sh_wsq[i] = v * v;
    }
    __syncthreads();

    const int lane = threadIdx.x & 31;
    const int q = lane >> 2;   // f sub-index within the j-group
    const int c = lane & 3;    // e-quarter / p-column
    const int warp = threadIdx.x >> 5;
    const int gwarp = blockIdx.x * (THREADS / 32) + warp;
    const int nwarp = BLOCKS * (THREADS / 32);

    for (int r = gwarp; r < R_ROWS; r += nwarp) {
        const float4* __restrict__ xr =
            reinterpret_cast<const float4*>(x + (size_t)r * (F_DIM * E_DIM));

        // All 8 loads issued up front; launch_bounds(256,4) -> 64 regs so
        // ptxas keeps the full 8-deep MLP in flight.
        float4 v[8];
#pragma unroll
        for (int j = 0; j < 8; ++j) {
            v[j] = __ldcs(&xr[j * 32 + lane]);
        }

        float acc0 = 0.0f, acc1 = 0.0f, acc2 = 0.0f;
#pragma unroll
        for (int j = 0; j < 8; ++j) {
            float4 a = v[j];
            float s = fmaf(a.x, a.x,
                      fmaf(a.y, a.y,
                      fmaf(a.z, a.z, a.w * a.w)));
            // complete sum over e (16 values span the 4 lanes of the quad)
            s += __shfl_xor_sync(0xFFFFFFFFu, s, 1);
            s += __shfl_xor_sync(0xFFFFFFFFu, s, 2);
            const float* wrow = &sh_wsq[(8 * j + q) * P_PAD + c];
            acc0 = fmaf(wrow[0], s, acc0);
            acc1 = fmaf(wrow[4], s, acc1);
            acc2 = fmaf(wrow[8], s, acc2);
        }

        // reduce across the 8 quads (sum over f-groups)
#pragma unroll
        for (int m = 4; m <= 16; m <<= 1) {
            acc0 += __shfl_xor_sync(0xFFFFFFFFu, acc0, m);
            acc1 += __shfl_xor_sync(0xFFFFFFFFu, acc1, m);
            acc2 += __shfl_xor_sync(0xFFFFFFFFu, acc2, m);
        }

        // lane = 4q + c = p for q<3; p=10,11 are padding -> lanes 0..9 store
        if (lane < P_DIM) {
            float res = (lane < 4) ? acc0 : (lane < 8) ? acc1 : acc2;
            out[(size_t)r * P_DIM + lane] = res;
        }
    }
}

extern "C" void kernel_launch(void* const* d_in, const int* in_sizes, int n_in,
                              void* d_out, int out_size)
{
    const float* x = (const float*)d_in[0];   // [32768, 64, 16]
    const float* w = (const float*)d_in[1];   // [10, 64]
    float* out = (float*)d_out;               // [32768, 10]
    (void)in_sizes; (void)n_in; (void)out_size;

    ip_fused_kernel<<<BLOCKS, THREADS>>>(x, w, out);
}